// round 11
// baseline (speedup 1.0000x reference)
#include <cuda_runtime.h>
#include <cuda_fp16.h>
#include <cstdint>

// Problem constants (fixed shapes from the reference)
#define NE      513              // NUM_EDGES + 1
#define LHOPS   5
#define HEADS   8
#define FEAT    64
#define NPAIRS  (8*128*128)      // 131072
#define TBL     (LHOPS*NE*HEADS) // 20520 halves = 41040 B
#define GRID    512              // 512 CTAs x 256 threads = exactly NPAIRS
#define BLOCK   256

// Precomputed projection table proj[l][e][h] in fp16 (L1-cached at gather time)
__device__ __align__(16) __half g_proj[TBL];

// Kernel A: proj[l][e][h] = sum_f edge_emb[e][f] * attn_w[l][f][h]
// grid=(17 e-tiles, 5 l), block=256 = 32e x 8h. PDL trigger at ENTRY so the
// consumer launches immediately. emb rows via broadcast LDG.128 (MLP 16);
// w[l] staged in smem (conflict-free 8-way broadcast reads).
__global__ void proj_kernel(const float* __restrict__ emb,
                            const float* __restrict__ w) {
#if __CUDA_ARCH__ >= 900
    cudaTriggerProgrammaticLaunchCompletion();   // let enc start NOW
#endif
    __shared__ __align__(16) float s_w[FEAT * HEADS];  // 2 KB
    const int l   = blockIdx.y;
    const int tid = threadIdx.x;

    for (int i = tid; i < FEAT * HEADS / 4; i += 256)
        ((float4*)s_w)[i] = ((const float4*)(w + l * FEAT * HEADS))[i];
    __syncthreads();

    const int e = blockIdx.x * 32 + (tid >> 3);
    const int h = tid & 7;
    if (e < NE) {
        const float4* em = (const float4*)(emb + (size_t)e * FEAT);
        float acc = 0.f;
        #pragma unroll
        for (int f4 = 0; f4 < 16; ++f4) {
            float4 ev = __ldg(em + f4);          // 8 threads share: broadcast
            acc = fmaf(ev.x, s_w[(f4 * 4 + 0) * HEADS + h], acc);
            acc = fmaf(ev.y, s_w[(f4 * 4 + 1) * HEADS + h], acc);
            acc = fmaf(ev.z, s_w[(f4 * 4 + 2) * HEADS + h], acc);
            acc = fmaf(ev.w, s_w[(f4 * 4 + 3) * HEADS + h], acc);
        }
        g_proj[(l * NE + e) * HEADS + h] = __float2half(acc);  // coalesced
    }
}

// Kernel B: NO smem table. 512 CTAs x 256 threads, one pair per thread,
// exactly covering NPAIRS (no predicates). Gathers hit the 41 KB table
// directly through L1 (228 KB, zero smem usage -> full carveout).
// Phase 0 (overlaps proj via PDL): pd + dist -> registers.
// Phase 1 (after griddepsync): 10 x LDG.128 gathers, HADD2 pairwise, fp32 acc.
__global__ void __launch_bounds__(BLOCK)
enc_kernel(const void* __restrict__ distp,
           const void* __restrict__ pdp,
           float* __restrict__ out) {
    const int pair = blockIdx.x * BLOCK + threadIdx.x;

    // dtype detection: dist in [1,5]; int64 (LE) => word #1 is high half == 0.
    const bool is64 = (((const int*)distp)[1] == 0);

    // ---- Phase 0: pd + dist loads into registers (overlap proj via PDL) ----
    int idx[2 * LHOPS];
    float scale;
    if (is64) {
        const int4* pp = (const int4*)((const long long*)pdp + (size_t)pair * 10);
        #pragma unroll
        for (int j = 0; j < 5; ++j) {
            int4 v = pp[j];              // low words of two int64: .x, .z
            idx[2 * j]     = v.x;
            idx[2 * j + 1] = v.z;
        }
        scale = __fdividef(0.5f, (float)((const int*)distp)[2 * pair]);
    } else {
        const int2* pp = (const int2*)((const int*)pdp + (size_t)pair * 10);
        #pragma unroll
        for (int j = 0; j < 5; ++j) {
            int2 v = pp[j];
            idx[2 * j]     = v.x;
            idx[2 * j + 1] = v.y;
        }
        scale = __fdividef(0.5f, (float)((const int*)distp)[pair]);
    }

#if __CUDA_ARCH__ >= 900
    cudaGridDependencySynchronize();     // g_proj ready (PDL)
#endif

    // ---- Phase 1: gather straight from L1-cached gmem table.
    // Hops 2q,2q+1 share level q: HADD2 pairwise, then fp32 accumulate.
    float4 al = make_float4(0.f, 0.f, 0.f, 0.f);
    float4 ah = al;
    #pragma unroll
    for (int q = 0; q < LHOPS; ++q) {
        const float4* base = (const float4*)(g_proj + q * NE * HEADS);
        float4 v0 = __ldg(base + idx[2 * q]);
        float4 v1 = __ldg(base + idx[2 * q + 1]);
        __half2 s0 = __hadd2(*(__half2*)&v0.x, *(__half2*)&v1.x);
        __half2 s1 = __hadd2(*(__half2*)&v0.y, *(__half2*)&v1.y);
        __half2 s2 = __hadd2(*(__half2*)&v0.z, *(__half2*)&v1.z);
        __half2 s3 = __hadd2(*(__half2*)&v0.w, *(__half2*)&v1.w);
        float2 f0 = __half22float2(s0);
        float2 f1 = __half22float2(s1);
        float2 f2 = __half22float2(s2);
        float2 f3 = __half22float2(s3);
        al.x += f0.x; al.y += f0.y; al.z += f1.x; al.w += f1.y;
        ah.x += f2.x; ah.y += f2.y; ah.z += f3.x; ah.w += f3.y;
    }

    float4* o = (float4*)(out + (size_t)pair * HEADS);
    o[0] = make_float4(al.x * scale, al.y * scale, al.z * scale, al.w * scale);
    o[1] = make_float4(ah.x * scale, ah.y * scale, ah.z * scale, ah.w * scale);
}

extern "C" void kernel_launch(void* const* d_in, const int* in_sizes, int n_in,
                              void* d_out, int out_size) {
    const void*  dist = d_in[0];
    const void*  pd   = d_in[1];
    const float* emb  = (const float*)d_in[2];
    const float* w    = (const float*)d_in[3];

    proj_kernel<<<dim3((NE + 31) / 32, LHOPS), 256>>>(emb, w);

    // PDL secondary: starts during proj (trigger at proj entry);
    // griddepsync guards g_proj reads.
    cudaLaunchConfig_t cfg = {};
    cfg.gridDim  = dim3(GRID);
    cfg.blockDim = dim3(BLOCK);
    cfg.dynamicSmemBytes = 0;
    cfg.stream = 0;
    cudaLaunchAttribute attr[1];
    attr[0].id = cudaLaunchAttributeProgrammaticStreamSerialization;
    attr[0].val.programmaticStreamSerializationAllowed = 1;
    cfg.attrs = attr;
    cfg.numAttrs = 1;
    cudaLaunchKernelEx(&cfg, enc_kernel, dist, pd, (float*)d_out);
}

// round 12
// speedup vs baseline: 1.0787x; 1.0787x over previous
#include <cuda_runtime.h>
#include <cuda_fp16.h>
#include <cstdint>

// Problem constants (fixed shapes from the reference)
#define NE      513              // NUM_EDGES + 1
#define LHOPS   5
#define HEADS   8
#define FEAT    64
#define NPAIRS  (8*128*128)      // 131072
#define TBL     (LHOPS*NE*HEADS) // 20520 halves = 41040 B
#define GRID    296              // 2 CTAs per SM
#define CHUNK   443              // ceil(NPAIRS / 296)

// Precomputed projection table proj[l][e][h] in fp16
__device__ __align__(16) __half g_proj[TBL];

// Kernel A: proj[l][e][h] = sum_f edge_emb[e][f] * attn_w[l][f][h]
// grid=(17 e-tiles, 5 l), block=256 = 32e x 8h. PDL trigger at ENTRY so the
// consumer launches immediately. emb rows via broadcast LDG.128 (MLP 16);
// w[l] staged in smem (conflict-free 8-way broadcast reads).
__global__ void proj_kernel(const float* __restrict__ emb,
                            const float* __restrict__ w) {
#if __CUDA_ARCH__ >= 900
    cudaTriggerProgrammaticLaunchCompletion();   // let enc start NOW
#endif
    __shared__ __align__(16) float s_w[FEAT * HEADS];  // 2 KB
    const int l   = blockIdx.y;
    const int tid = threadIdx.x;

    for (int i = tid; i < FEAT * HEADS / 4; i += 256)
        ((float4*)s_w)[i] = ((const float4*)(w + l * FEAT * HEADS))[i];
    __syncthreads();

    const int e = blockIdx.x * 32 + (tid >> 3);
    const int h = tid & 7;
    if (e < NE) {
        const float4* em = (const float4*)(emb + (size_t)e * FEAT);
        float acc = 0.f;
        #pragma unroll
        for (int f4 = 0; f4 < 16; ++f4) {
            float4 ev = __ldg(em + f4);          // 8 threads share: broadcast
            acc = fmaf(ev.x, s_w[(f4 * 4 + 0) * HEADS + h], acc);
            acc = fmaf(ev.y, s_w[(f4 * 4 + 1) * HEADS + h], acc);
            acc = fmaf(ev.z, s_w[(f4 * 4 + 2) * HEADS + h], acc);
            acc = fmaf(ev.w, s_w[(f4 * 4 + 3) * HEADS + h], acc);
        }
        g_proj[(l * NE + e) * HEADS + h] = __float2half(acc);  // coalesced
    }
}

// Kernel B: 296 CTAs = 2 per SM (64 warps/SM, max thread occupancy; regs
// capped at 32 by launch_bounds). Two co-resident CTAs give independent
// barrier domains so staging/gather/store phases of the two CTAs overlap.
// Phase 0 (overlaps proj via PDL): pd + dist -> registers.
// Phase 1 (after griddepsync): cooperative 41 KB fp16 table staging.
// Phase 2: gather — one LDS.128 per (pair,hop), HADD2 pairwise, fp32 accum.
__global__ void __launch_bounds__(1024, 2)
enc_kernel(const void* __restrict__ distp,
           const void* __restrict__ pdp,
           float* __restrict__ out) {
    __shared__ __align__(16) __half s_tbl[TBL];  // 41040 B static
    const int tid  = threadIdx.x;
    const int pair = blockIdx.x * CHUNK + tid;
    const bool act = (tid < CHUNK) && (pair < NPAIRS);
    const int p    = act ? pair : blockIdx.x * CHUNK;  // clamp: loads unconditional

    // dtype detection: dist in [1,5]; int64 (LE) => word #1 is high half == 0.
    const bool is64 = (((const int*)distp)[1] == 0);

    // ---- Phase 0: pd + dist loads into registers (overlap proj via PDL) ----
    int idx[2 * LHOPS];
    float scale;
    if (is64) {
        const int4* pp = (const int4*)((const long long*)pdp + (size_t)p * 10);
        #pragma unroll
        for (int j = 0; j < 5; ++j) {
            int4 v = pp[j];              // low words of two int64: .x, .z
            idx[2 * j]     = v.x;
            idx[2 * j + 1] = v.z;
        }
        scale = __fdividef(0.5f, (float)((const int*)distp)[2 * p]);
    } else {
        const int2* pp = (const int2*)((const int*)pdp + (size_t)p * 10);
        #pragma unroll
        for (int j = 0; j < 5; ++j) {
            int2 v = pp[j];
            idx[2 * j]     = v.x;
            idx[2 * j + 1] = v.y;
        }
        scale = __fdividef(0.5f, (float)((const int*)distp)[p]);
    }

#if __CUDA_ARCH__ >= 900
    cudaGridDependencySynchronize();     // g_proj ready (PDL)
#endif

    // ---- Phase 1: stage fp16 table (41040 B = 2565 x 16B) ----
    {
        const float4* gsrc = (const float4*)g_proj;
        float4* sdst = (float4*)s_tbl;
        #pragma unroll
        for (int r = 0; r < 3; ++r) {
            int i = tid + r * 1024;
            if (i < TBL / 8) sdst[i] = gsrc[i];
        }
    }
    __syncthreads();

    // ---- Phase 2: gather. Hops 2q,2q+1 share level q: HADD2 pairwise,
    // then fp32 accumulate.
    if (act) {
        float4 al = make_float4(0.f, 0.f, 0.f, 0.f);
        float4 ah = al;
        #pragma unroll
        for (int q = 0; q < LHOPS; ++q) {
            const __half* base = s_tbl + q * NE * HEADS;
            float4 v0 = *(const float4*)(base + idx[2 * q]     * HEADS);
            float4 v1 = *(const float4*)(base + idx[2 * q + 1] * HEADS);
            __half2 s0 = __hadd2(*(__half2*)&v0.x, *(__half2*)&v1.x);
            __half2 s1 = __hadd2(*(__half2*)&v0.y, *(__half2*)&v1.y);
            __half2 s2 = __hadd2(*(__half2*)&v0.z, *(__half2*)&v1.z);
            __half2 s3 = __hadd2(*(__half2*)&v0.w, *(__half2*)&v1.w);
            float2 f0 = __half22float2(s0);
            float2 f1 = __half22float2(s1);
            float2 f2 = __half22float2(s2);
            float2 f3 = __half22float2(s3);
            al.x += f0.x; al.y += f0.y; al.z += f1.x; al.w += f1.y;
            ah.x += f2.x; ah.y += f2.y; ah.z += f3.x; ah.w += f3.y;
        }
        float4* o = (float4*)(out + (size_t)p * HEADS);
        o[0] = make_float4(al.x * scale, al.y * scale, al.z * scale, al.w * scale);
        o[1] = make_float4(ah.x * scale, ah.y * scale, ah.z * scale, ah.w * scale);
    }
}

extern "C" void kernel_launch(void* const* d_in, const int* in_sizes, int n_in,
                              void* d_out, int out_size) {
    const void*  dist = d_in[0];
    const void*  pd   = d_in[1];
    const float* emb  = (const float*)d_in[2];
    const float* w    = (const float*)d_in[3];

    proj_kernel<<<dim3((NE + 31) / 32, LHOPS), 256>>>(emb, w);

    // PDL secondary: starts during proj (trigger at proj entry);
    // griddepsync guards g_proj reads.
    cudaLaunchConfig_t cfg = {};
    cfg.gridDim  = dim3(GRID);
    cfg.blockDim = dim3(1024);
    cfg.dynamicSmemBytes = 0;
    cfg.stream = 0;
    cudaLaunchAttribute attr[1];
    attr[0].id = cudaLaunchAttributeProgrammaticStreamSerialization;
    attr[0].val.programmaticStreamSerializationAllowed = 1;
    cfg.attrs = attr;
    cfg.numAttrs = 1;
    cudaLaunchKernelEx(&cfg, enc_kernel, dist, pd, (float*)d_out);
}

// round 13
// speedup vs baseline: 1.1563x; 1.0719x over previous
#include <cuda_runtime.h>
#include <cuda_fp16.h>
#include <cstdint>

// Problem constants (fixed shapes from the reference)
#define NE      513              // NUM_EDGES + 1
#define LHOPS   5
#define HEADS   8
#define FEAT    64
#define NPAIRS  (8*128*128)      // 131072
#define TBL     (LHOPS*NE*HEADS) // 20520 halves = 41040 B
#define GRID    296              // 2 CTAs per SM
#define BLOCK   832              // 2*832 + 256 (proj) = 1920 <= 2048 slots/SM
#define CHUNK   443              // ceil(NPAIRS / 296)

// Precomputed projection table proj[l][e][h] in fp16
__device__ __align__(16) __half g_proj[TBL];

// Kernel A: proj[l][e][h] = sum_f edge_emb[e][f] * attn_w[l][f][h]
// grid=(17 e-tiles, 5 l), block=256 = 32e x 8h. PDL trigger at ENTRY so the
// consumer launches immediately. emb rows via broadcast LDG.128 (MLP 16);
// w[l] staged in smem (conflict-free 8-way broadcast reads).
__global__ void proj_kernel(const float* __restrict__ emb,
                            const float* __restrict__ w) {
#if __CUDA_ARCH__ >= 900
    cudaTriggerProgrammaticLaunchCompletion();   // let enc start NOW
#endif
    __shared__ __align__(16) float s_w[FEAT * HEADS];  // 2 KB
    const int l   = blockIdx.y;
    const int tid = threadIdx.x;

    for (int i = tid; i < FEAT * HEADS / 4; i += 256)
        ((float4*)s_w)[i] = ((const float4*)(w + l * FEAT * HEADS))[i];
    __syncthreads();

    const int e = blockIdx.x * 32 + (tid >> 3);
    const int h = tid & 7;
    if (e < NE) {
        const float4* em = (const float4*)(emb + (size_t)e * FEAT);
        float acc = 0.f;
        #pragma unroll
        for (int f4 = 0; f4 < 16; ++f4) {
            float4 ev = __ldg(em + f4);          // 8 threads share: broadcast
            acc = fmaf(ev.x, s_w[(f4 * 4 + 0) * HEADS + h], acc);
            acc = fmaf(ev.y, s_w[(f4 * 4 + 1) * HEADS + h], acc);
            acc = fmaf(ev.z, s_w[(f4 * 4 + 2) * HEADS + h], acc);
            acc = fmaf(ev.w, s_w[(f4 * 4 + 3) * HEADS + h], acc);
        }
        g_proj[(l * NE + e) * HEADS + h] = __float2half(acc);  // coalesced
    }
}

// Kernel B: 296 CTAs = 2 per SM at 832 threads each. 2*832 + proj's 256 fits
// the 2048 thread slots, so ALL enc CTAs are co-resident with proj (preload
// overlap) AND the two CTAs' staging/gather phases interleave (independent
// barrier domains).
// Phase 0 (overlaps proj via PDL): pd + dist -> registers.
// Phase 1 (after griddepsync): cooperative 41 KB fp16 table staging.
// Phase 2: gather — one LDS.128 per (pair,hop), HADD2 pairwise, fp32 accum.
__global__ void __launch_bounds__(BLOCK, 2)
enc_kernel(const void* __restrict__ distp,
           const void* __restrict__ pdp,
           float* __restrict__ out) {
    __shared__ __align__(16) __half s_tbl[TBL];  // 41040 B static
    const int tid  = threadIdx.x;
    const int pair = blockIdx.x * CHUNK + tid;
    const bool act = (tid < CHUNK) && (pair < NPAIRS);
    const int p    = act ? pair : blockIdx.x * CHUNK;  // clamp: loads unconditional

    // dtype detection: dist in [1,5]; int64 (LE) => word #1 is high half == 0.
    const bool is64 = (((const int*)distp)[1] == 0);

    // ---- Phase 0: pd + dist loads into registers (overlap proj via PDL) ----
    int idx[2 * LHOPS];
    float scale;
    if (is64) {
        const int4* pp = (const int4*)((const long long*)pdp + (size_t)p * 10);
        #pragma unroll
        for (int j = 0; j < 5; ++j) {
            int4 v = pp[j];              // low words of two int64: .x, .z
            idx[2 * j]     = v.x;
            idx[2 * j + 1] = v.z;
        }
        scale = __fdividef(0.5f, (float)((const int*)distp)[2 * p]);
    } else {
        const int2* pp = (const int2*)((const int*)pdp + (size_t)p * 10);
        #pragma unroll
        for (int j = 0; j < 5; ++j) {
            int2 v = pp[j];
            idx[2 * j]     = v.x;
            idx[2 * j + 1] = v.y;
        }
        scale = __fdividef(0.5f, (float)((const int*)distp)[p]);
    }

#if __CUDA_ARCH__ >= 900
    cudaGridDependencySynchronize();     // g_proj ready (PDL)
#endif

    // ---- Phase 1: stage fp16 table (41040 B = 2565 x 16B) ----
    {
        const float4* gsrc = (const float4*)g_proj;
        float4* sdst = (float4*)s_tbl;
        #pragma unroll
        for (int r = 0; r < 4; ++r) {
            int i = tid + r * BLOCK;
            if (i < TBL / 8) sdst[i] = gsrc[i];
        }
    }
    __syncthreads();

    // ---- Phase 2: gather. Hops 2q,2q+1 share level q: HADD2 pairwise,
    // then fp32 accumulate.
    if (act) {
        float4 al = make_float4(0.f, 0.f, 0.f, 0.f);
        float4 ah = al;
        #pragma unroll
        for (int q = 0; q < LHOPS; ++q) {
            const __half* base = s_tbl + q * NE * HEADS;
            float4 v0 = *(const float4*)(base + idx[2 * q]     * HEADS);
            float4 v1 = *(const float4*)(base + idx[2 * q + 1] * HEADS);
            __half2 s0 = __hadd2(*(__half2*)&v0.x, *(__half2*)&v1.x);
            __half2 s1 = __hadd2(*(__half2*)&v0.y, *(__half2*)&v1.y);
            __half2 s2 = __hadd2(*(__half2*)&v0.z, *(__half2*)&v1.z);
            __half2 s3 = __hadd2(*(__half2*)&v0.w, *(__half2*)&v1.w);
            float2 f0 = __half22float2(s0);
            float2 f1 = __half22float2(s1);
            float2 f2 = __half22float2(s2);
            float2 f3 = __half22float2(s3);
            al.x += f0.x; al.y += f0.y; al.z += f1.x; al.w += f1.y;
            ah.x += f2.x; ah.y += f2.y; ah.z += f3.x; ah.w += f3.y;
        }
        float4* o = (float4*)(out + (size_t)p * HEADS);
        o[0] = make_float4(al.x * scale, al.y * scale, al.z * scale, al.w * scale);
        o[1] = make_float4(ah.x * scale, ah.y * scale, ah.z * scale, ah.w * scale);
    }
}

extern "C" void kernel_launch(void* const* d_in, const int* in_sizes, int n_in,
                              void* d_out, int out_size) {
    const void*  dist = d_in[0];
    const void*  pd   = d_in[1];
    const float* emb  = (const float*)d_in[2];
    const float* w    = (const float*)d_in[3];

    proj_kernel<<<dim3((NE + 31) / 32, LHOPS), 256>>>(emb, w);

    // PDL secondary: starts during proj (trigger at proj entry);
    // griddepsync guards g_proj reads.
    cudaLaunchConfig_t cfg = {};
    cfg.gridDim  = dim3(GRID);
    cfg.blockDim = dim3(BLOCK);
    cfg.dynamicSmemBytes = 0;
    cfg.stream = 0;
    cudaLaunchAttribute attr[1];
    attr[0].id = cudaLaunchAttributeProgrammaticStreamSerialization;
    attr[0].val.programmaticStreamSerializationAllowed = 1;
    cfg.attrs = attr;
    cfg.numAttrs = 1;
    cudaLaunchKernelEx(&cfg, enc_kernel, dist, pd, (float*)d_out);
}